// round 16
// baseline (speedup 1.0000x reference)
#include <cuda_runtime.h>

#define NN 50000
#define EE 800000
#define CAP 96
#define TPB 256

// ---------------- scratch (static device globals; no allocation) ----------------
// g_cur starts zeroed (.bss) and is re-zeroed by the FINAL gather each execution,
// so no memset node is needed in the graph.
__device__ int   g_cur[NN];
__device__ int   g_srcl[NN * CAP];
__device__ float g_dinv[NN];
__device__ float g_xw[NN * 64];     // pre-scaled by dinv[row]
__device__ float g_x1[NN * 64];
__device__ float g_q[NN * 64];      // pre-scaled by 0.125
__device__ float g_k[NN * 64];
__device__ float g_v[NN * 64];
__device__ float g_x2[NN * 64];

// ---------------- f32x2 helpers ----------------
__device__ __forceinline__ unsigned long long splat2(float x) {
    unsigned long long r;
    asm("mov.b64 %0, {%1, %1};" : "=l"(r) : "f"(x));
    return r;
}
__device__ __forceinline__ unsigned long long fma2(unsigned long long a,
                                                   unsigned long long b,
                                                   unsigned long long c) {
    unsigned long long d;
    asm("fma.rn.f32x2 %0, %1, %2, %3;" : "=l"(d) : "l"(a), "l"(b), "l"(c));
    return d;
}

// ---------------- bucket CSR build (single edge pass, 2 edges/thread) ------------
__global__ void k_fill(const int* __restrict__ ei, int e) {
    int id = (blockIdx.x * blockDim.x + threadIdx.x) * 2;
    if (id + 1 < e) {
        int2 s2 = *(const int2*)(ei + id);
        int2 d2 = *(const int2*)(ei + e + id);
        int r0 = atomicAdd(&g_cur[d2.x], 1);
        if (r0 < CAP) g_srcl[d2.x * CAP + r0] = s2.x;
        int r1 = atomicAdd(&g_cur[d2.y], 1);
        if (r1 < CAP) g_srcl[d2.y * CAP + r1] = s2.y;
    } else if (id < e) {
        int s = ei[id];
        int d = ei[e + id];
        int r = atomicAdd(&g_cur[d], 1);
        if (r < CAP) g_srcl[d * CAP + r] = s;
    }
}

// ------- GCN gather: warp per dst, two 16-lane halves. RESET=true (final pass)
// zeroes g_cur[w] after use so the next graph replay starts from clean cursors. ----
template <bool RESET>
__global__ __launch_bounds__(256) void k_gcn_gather(const float* __restrict__ xw,
                                                    const float* __restrict__ bias,
                                                    float* __restrict__ out, int n) {
    int w = (blockIdx.x * blockDim.x + threadIdx.x) >> 5;
    if (w >= n) return;
    int lane = threadIdx.x & 31;
    int half = lane >> 4;
    int hl = lane & 15;
    int cnt = g_cur[w];
    if (RESET) {
        if (lane == 0) g_cur[w] = 0;
    }
    if (cnt > CAP) cnt = CAP;
    const int* sl = g_srcl + w * CAP;
    float4 acc = make_float4(0.f, 0.f, 0.f, 0.f);
    int j = half;
    for (; j + 6 < cnt; j += 8) {
        int s0 = sl[j], s1 = sl[j + 2], s2 = sl[j + 4], s3 = sl[j + 6];
        float4 a0 = *(const float4*)(xw + s0 * 64 + hl * 4);
        float4 a1 = *(const float4*)(xw + s1 * 64 + hl * 4);
        float4 a2 = *(const float4*)(xw + s2 * 64 + hl * 4);
        float4 a3 = *(const float4*)(xw + s3 * 64 + hl * 4);
        acc.x += (a0.x + a1.x) + (a2.x + a3.x);
        acc.y += (a0.y + a1.y) + (a2.y + a3.y);
        acc.z += (a0.z + a1.z) + (a2.z + a3.z);
        acc.w += (a0.w + a1.w) + (a2.w + a3.w);
    }
    for (; j < cnt; j += 2) {
        int s = sl[j];
        float4 a = *(const float4*)(xw + s * 64 + hl * 4);
        acc.x += a.x; acc.y += a.y; acc.z += a.z; acc.w += a.w;
    }
    acc.x += __shfl_xor_sync(0xffffffffu, acc.x, 16);
    acc.y += __shfl_xor_sync(0xffffffffu, acc.y, 16);
    acc.z += __shfl_xor_sync(0xffffffffu, acc.z, 16);
    acc.w += __shfl_xor_sync(0xffffffffu, acc.w, 16);
    if (half == 0) {
        float dd = g_dinv[w];
        float4 sv = *(const float4*)(xw + w * 64 + hl * 4);
        float4 b = *(const float4*)(bias + hl * 4);
        float4 o = make_float4((acc.x + sv.x) * dd + b.x, (acc.y + sv.y) * dd + b.y,
                               (acc.z + sv.z) * dd + b.z, (acc.w + sv.w) * dd + b.w);
        *(float4*)(out + w * 64 + hl * 4) = o;
    }
}

// ---------------- fused attention: warp per dst, per-half masks in loops (R6) ----
__global__ __launch_bounds__(256) void k_attn(int n) {
    int w = (blockIdx.x * blockDim.x + threadIdx.x) >> 5;
    if (w >= n) return;
    int lane = threadIdx.x & 31;
    int half = lane >> 4;
    int hl = lane & 15;
    unsigned hmask = half ? 0xffff0000u : 0x0000ffffu;
    int cnt = g_cur[w];
    if (cnt > CAP) cnt = CAP;
    const int* sl = g_srcl + w * CAP;
    float4 q4 = *(const float4*)(g_q + w * 64 + hl * 4);
    float z = 0.f;
    float4 acc = make_float4(0.f, 0.f, 0.f, 0.f);
    int j = half;
    for (; j + 6 < cnt; j += 8) {
        int s0 = sl[j], s1 = sl[j + 2], s2 = sl[j + 4], s3 = sl[j + 6];
        float4 k0 = *(const float4*)(g_k + s0 * 64 + hl * 4);
        float4 k1 = *(const float4*)(g_k + s1 * 64 + hl * 4);
        float4 k2 = *(const float4*)(g_k + s2 * 64 + hl * 4);
        float4 k3 = *(const float4*)(g_k + s3 * 64 + hl * 4);
        float4 v0 = *(const float4*)(g_v + s0 * 64 + hl * 4);
        float4 v1 = *(const float4*)(g_v + s1 * 64 + hl * 4);
        float4 v2 = *(const float4*)(g_v + s2 * 64 + hl * 4);
        float4 v3 = *(const float4*)(g_v + s3 * 64 + hl * 4);
        float p0 = q4.x * k0.x + q4.y * k0.y + q4.z * k0.z + q4.w * k0.w;
        float p1 = q4.x * k1.x + q4.y * k1.y + q4.z * k1.z + q4.w * k1.w;
        float p2 = q4.x * k2.x + q4.y * k2.y + q4.z * k2.z + q4.w * k2.w;
        float p3 = q4.x * k3.x + q4.y * k3.y + q4.z * k3.z + q4.w * k3.w;
#pragma unroll
        for (int o = 8; o > 0; o >>= 1) {
            p0 += __shfl_xor_sync(hmask, p0, o);
            p1 += __shfl_xor_sync(hmask, p1, o);
            p2 += __shfl_xor_sync(hmask, p2, o);
            p3 += __shfl_xor_sync(hmask, p3, o);
        }
        float e0 = __expf(p0), e1 = __expf(p1);
        float e2 = __expf(p2), e3 = __expf(p3);
        z += (e0 + e1) + (e2 + e3);
        acc.x += (v0.x * e0 + v1.x * e1) + (v2.x * e2 + v3.x * e3);
        acc.y += (v0.y * e0 + v1.y * e1) + (v2.y * e2 + v3.y * e3);
        acc.z += (v0.z * e0 + v1.z * e1) + (v2.z * e2 + v3.z * e3);
        acc.w += (v0.w * e0 + v1.w * e1) + (v2.w * e2 + v3.w * e3);
    }
    for (; j < cnt; j += 2) {
        int s = sl[j];
        float4 kv = *(const float4*)(g_k + s * 64 + hl * 4);
        float4 vv = *(const float4*)(g_v + s * 64 + hl * 4);
        float p = q4.x * kv.x + q4.y * kv.y + q4.z * kv.z + q4.w * kv.w;
#pragma unroll
        for (int o = 8; o > 0; o >>= 1) p += __shfl_xor_sync(hmask, p, o);
        float ev = __expf(p);
        z += ev;
        acc.x += vv.x * ev; acc.y += vv.y * ev; acc.z += vv.z * ev; acc.w += vv.w * ev;
    }
    z += __shfl_xor_sync(0xffffffffu, z, 16);
    acc.x += __shfl_xor_sync(0xffffffffu, acc.x, 16);
    acc.y += __shfl_xor_sync(0xffffffffu, acc.y, 16);
    acc.z += __shfl_xor_sync(0xffffffffu, acc.z, 16);
    acc.w += __shfl_xor_sync(0xffffffffu, acc.w, 16);
    if (half == 0) {
        float4 o = *(float4*)(g_x2 + w * 64 + hl * 4);
        if (z > 0.f) {
            float inv = 1.f / z;
            o.x += acc.x * inv; o.y += acc.y * inv;
            o.z += acc.z * inv; o.w += acc.w * inv;
        }
        *(float4*)(g_x2 + w * 64 + hl * 4) = o;
    }
}

// ---- f32x2 GEMM (R6 core). DINV=true: compute sc=rsqrt(g_cur[row]+1), store to
// g_dinv, and prescale (GCN1 path). DINV=false: read rscale (GCN2 path). ----------
template <bool DINV>
__global__ __launch_bounds__(256) void k_gemm2(const float* __restrict__ A,
                                               const float* __restrict__ W,
                                               const float* __restrict__ rscale,
                                               float* __restrict__ C, int n) {
    __shared__ float Ast[64][128];
    __shared__ float Wsm[64][64];
    int tid = threadIdx.x;
    int base = blockIdx.x * 128;
    {
        int wr = tid >> 2, wc = (tid & 3) * 16;
#pragma unroll
        for (int j = 0; j < 4; j++)
            *(float4*)&Wsm[wr][wc + j * 4] = *(const float4*)(W + wr * 64 + wc + j * 4);
    }
    {
        int lr = tid >> 1;
        int lc = (tid & 1) * 32;
        int grow = base + lr;
#pragma unroll
        for (int j = 0; j < 8; j++) {
            float4 a = make_float4(0.f, 0.f, 0.f, 0.f);
            if (grow < n) a = *(const float4*)(A + grow * 64 + lc + j * 4);
            Ast[lc + j * 4 + 0][lr] = a.x;
            Ast[lc + j * 4 + 1][lr] = a.y;
            Ast[lc + j * 4 + 2][lr] = a.z;
            Ast[lc + j * 4 + 3][lr] = a.w;
        }
    }
    __syncthreads();
    int tx = tid & 15, ty = tid >> 4;
    unsigned long long acc[4][4];
#pragma unroll
    for (int i = 0; i < 4; i++)
#pragma unroll
        for (int j = 0; j < 4; j++) acc[i][j] = 0ull;
#pragma unroll 8
    for (int k = 0; k < 64; k++) {
        ulonglong2 ap0 = *(const ulonglong2*)&Ast[k][ty * 8];
        ulonglong2 ap1 = *(const ulonglong2*)&Ast[k][ty * 8 + 4];
        float4 w4 = *(const float4*)&Wsm[k][tx * 4];
        unsigned long long ws0 = splat2(w4.x), ws1 = splat2(w4.y);
        unsigned long long ws2 = splat2(w4.z), ws3 = splat2(w4.w);
        acc[0][0] = fma2(ap0.x, ws0, acc[0][0]);
        acc[0][1] = fma2(ap0.x, ws1, acc[0][1]);
        acc[0][2] = fma2(ap0.x, ws2, acc[0][2]);
        acc[0][3] = fma2(ap0.x, ws3, acc[0][3]);
        acc[1][0] = fma2(ap0.y, ws0, acc[1][0]);
        acc[1][1] = fma2(ap0.y, ws1, acc[1][1]);
        acc[1][2] = fma2(ap0.y, ws2, acc[1][2]);
        acc[1][3] = fma2(ap0.y, ws3, acc[1][3]);
        acc[2][0] = fma2(ap1.x, ws0, acc[2][0]);
        acc[2][1] = fma2(ap1.x, ws1, acc[2][1]);
        acc[2][2] = fma2(ap1.x, ws2, acc[2][2]);
        acc[2][3] = fma2(ap1.x, ws3, acc[2][3]);
        acc[3][0] = fma2(ap1.y, ws0, acc[3][0]);
        acc[3][1] = fma2(ap1.y, ws1, acc[3][1]);
        acc[3][2] = fma2(ap1.y, ws2, acc[3][2]);
        acc[3][3] = fma2(ap1.y, ws3, acc[3][3]);
    }
#pragma unroll
    for (int rp = 0; rp < 4; rp++) {
        float2 c0 = *(float2*)&acc[rp][0];
        float2 c1 = *(float2*)&acc[rp][1];
        float2 c2 = *(float2*)&acc[rp][2];
        float2 c3 = *(float2*)&acc[rp][3];
        int r0 = base + ty * 8 + rp * 2;
        if (r0 < n) {
            float sc;
            if (DINV) {
                sc = rsqrtf((float)(g_cur[r0] + 1));
                if (tx == 0) g_dinv[r0] = sc;
            } else {
                sc = rscale[r0];
            }
            float4 o = make_float4(c0.x * sc, c1.x * sc, c2.x * sc, c3.x * sc);
            *(float4*)(C + r0 * 64 + tx * 4) = o;
        }
        if (r0 + 1 < n) {
            float sc;
            if (DINV) {
                sc = rsqrtf((float)(g_cur[r0 + 1] + 1));
                if (tx == 0) g_dinv[r0 + 1] = sc;
            } else {
                sc = rscale[r0 + 1];
            }
            float4 o = make_float4(c0.y * sc, c1.y * sc, c2.y * sc, c3.y * sc);
            *(float4*)(C + (r0 + 1) * 64 + tx * 4) = o;
        }
    }
}

// ---------------- QKVS GEMM (R6 serial version, proven) ----------------
__global__ __launch_bounds__(256) void k_gemm_qkvs2(const float* __restrict__ A,
        const float* __restrict__ Wq, const float* __restrict__ bq,
        const float* __restrict__ Wk, const float* __restrict__ bk,
        const float* __restrict__ Wv, const float* __restrict__ bv,
        const float* __restrict__ Ws, const float* __restrict__ bs,
        float* __restrict__ Oq, float* __restrict__ Ok,
        float* __restrict__ Ov, float* __restrict__ Os, int n) {
    __shared__ float Ast[64][128];
    __shared__ float Wsm[64][64];
    int tid = threadIdx.x;
    int base = blockIdx.x * 128;
    {
        int lr = tid >> 1;
        int lc = (tid & 1) * 32;
        int grow = base + lr;
#pragma unroll
        for (int j = 0; j < 8; j++) {
            float4 a = make_float4(0.f, 0.f, 0.f, 0.f);
            if (grow < n) a = *(const float4*)(A + grow * 64 + lc + j * 4);
            Ast[lc + j * 4 + 0][lr] = fmaxf(a.x, 0.f);
            Ast[lc + j * 4 + 1][lr] = fmaxf(a.y, 0.f);
            Ast[lc + j * 4 + 2][lr] = fmaxf(a.z, 0.f);
            Ast[lc + j * 4 + 3][lr] = fmaxf(a.w, 0.f);
        }
    }
    int tx = tid & 15, ty = tid >> 4;
    const float* WL[4] = {Wq, Wk, Wv, Ws};
    const float* BL[4] = {bq, bk, bv, bs};
    float*       OL[4] = {Oq, Ok, Ov, Os};
#pragma unroll
    for (int ws = 0; ws < 4; ws++) {
        __syncthreads();
        {
            int wr = tid >> 2, wc = (tid & 3) * 16;
#pragma unroll
            for (int j = 0; j < 4; j++)
                *(float4*)&Wsm[wr][wc + j * 4] =
                    *(const float4*)(WL[ws] + wr * 64 + wc + j * 4);
        }
        __syncthreads();
        unsigned long long acc[4][4];
#pragma unroll
        for (int i = 0; i < 4; i++)
#pragma unroll
            for (int j = 0; j < 4; j++) acc[i][j] = 0ull;
#pragma unroll 8
        for (int k = 0; k < 64; k++) {
            ulonglong2 ap0 = *(const ulonglong2*)&Ast[k][ty * 8];
            ulonglong2 ap1 = *(const ulonglong2*)&Ast[k][ty * 8 + 4];
            float4 w4 = *(const float4*)&Wsm[k][tx * 4];
            unsigned long long s0 = splat2(w4.x), s1 = splat2(w4.y);
            unsigned long long s2 = splat2(w4.z), s3 = splat2(w4.w);
            acc[0][0] = fma2(ap0.x, s0, acc[0][0]);
            acc[0][1] = fma2(ap0.x, s1, acc[0][1]);
            acc[0][2] = fma2(ap0.x, s2, acc[0][2]);
            acc[0][3] = fma2(ap0.x, s3, acc[0][3]);
            acc[1][0] = fma2(ap0.y, s0, acc[1][0]);
            acc[1][1] = fma2(ap0.y, s1, acc[1][1]);
            acc[1][2] = fma2(ap0.y, s2, acc[1][2]);
            acc[1][3] = fma2(ap0.y, s3, acc[1][3]);
            acc[2][0] = fma2(ap1.x, s0, acc[2][0]);
            acc[2][1] = fma2(ap1.x, s1, acc[2][1]);
            acc[2][2] = fma2(ap1.x, s2, acc[2][2]);
            acc[2][3] = fma2(ap1.x, s3, acc[2][3]);
            acc[3][0] = fma2(ap1.y, s0, acc[3][0]);
            acc[3][1] = fma2(ap1.y, s1, acc[3][1]);
            acc[3][2] = fma2(ap1.y, s2, acc[3][2]);
            acc[3][3] = fma2(ap1.y, s3, acc[3][3]);
        }
        float osc = (ws == 0) ? 0.125f : 1.0f;
        float4 b4 = *(const float4*)(BL[ws] + tx * 4);
        float* Co = OL[ws];
#pragma unroll
        for (int rp = 0; rp < 4; rp++) {
            float2 c0 = *(float2*)&acc[rp][0];
            float2 c1 = *(float2*)&acc[rp][1];
            float2 c2 = *(float2*)&acc[rp][2];
            float2 c3 = *(float2*)&acc[rp][3];
            int r0 = base + ty * 8 + rp * 2;
            if (r0 < n) {
                float4 o = make_float4((c0.x + b4.x) * osc, (c1.x + b4.y) * osc,
                                       (c2.x + b4.z) * osc, (c3.x + b4.w) * osc);
                *(float4*)(Co + r0 * 64 + tx * 4) = o;
            }
            if (r0 + 1 < n) {
                float4 o = make_float4((c0.y + b4.x) * osc, (c1.y + b4.y) * osc,
                                       (c2.y + b4.z) * osc, (c3.y + b4.w) * osc);
                *(float4*)(Co + (r0 + 1) * 64 + tx * 4) = o;
            }
        }
    }
}

// ---------------- launch ----------------
extern "C" void kernel_launch(void* const* d_in, const int* in_sizes, int n_in,
                              void* d_out, int out_size) {
    const float* x  = (const float*)d_in[0];
    const int*   ei = (const int*)d_in[1];
    const float* W1 = (const float*)d_in[2];
    const float* b1 = (const float*)d_in[3];
    const float* Wq = (const float*)d_in[4];
    const float* bq = (const float*)d_in[5];
    const float* Wk = (const float*)d_in[6];
    const float* bk = (const float*)d_in[7];
    const float* Wv = (const float*)d_in[8];
    const float* bv = (const float*)d_in[9];
    const float* Ws = (const float*)d_in[10];
    const float* bs = (const float*)d_in[11];
    const float* W2 = (const float*)d_in[12];
    const float* b2 = (const float*)d_in[13];
    float* out = (float*)d_out;

    int n = in_sizes[0] / 64;
    int e = in_sizes[1] / 2;

    float *p_xw, *p_x1, *p_q, *p_k, *p_v, *p_x2, *p_dinv;
    cudaGetSymbolAddress((void**)&p_xw,  g_xw);
    cudaGetSymbolAddress((void**)&p_x1,  g_x1);
    cudaGetSymbolAddress((void**)&p_q,   g_q);
    cudaGetSymbolAddress((void**)&p_k,   g_k);
    cudaGetSymbolAddress((void**)&p_v,   g_v);
    cudaGetSymbolAddress((void**)&p_x2,  g_x2);
    cudaGetSymbolAddress((void**)&p_dinv, g_dinv);

    int ebk2 = (e / 2 + TPB) / TPB;
    int gb  = (n + 127) / 128;
    int wb  = (n + 7) / 8;

    // CSR build: single vectorized fill pass (cursors zeroed by previous run's
    // final gather; .bss zero-init covers the first run)
    k_fill<<<ebk2, TPB>>>(ei, e);

    // GCN1: xw = (x@W1) * rsqrt(deg+1); GEMM also writes g_dinv
    k_gemm2<true><<<gb, 256>>>(x, W1, nullptr, p_xw, n);
    k_gcn_gather<false><<<wb, 256>>>(p_xw, b1, p_x1, n);

    // TransformerConv (relu fused into A-load; q pre-scaled by 0.125)
    k_gemm_qkvs2<<<gb, 256>>>(p_x1, Wq, bq, Wk, bk, Wv, bv, Ws, bs,
                              p_q, p_k, p_v, p_x2, n);
    k_attn<<<wb, 256>>>(n);

    // GCN2 (reads g_dinv written by GEMM1); final gather resets g_cur for next replay
    k_gemm2<false><<<gb, 256>>>(p_x2, W2, p_dinv, p_xw, n);
    k_gcn_gather<true><<<wb, 256>>>(p_xw, b2, out, n);
}

// round 17
// speedup vs baseline: 1.5056x; 1.5056x over previous
#include <cuda_runtime.h>

#define NN 50000
#define EE 800000
#define CAP 96
#define TPB 256

// ---------------- scratch (static device globals; no allocation) ----------------
__device__ int   g_cur[NN];
__device__ int   g_srcl[NN * CAP];
__device__ float g_dinv[NN];
__device__ float g_xw[NN * 64];     // pre-scaled by dinv[row]
__device__ float g_x1[NN * 64];
__device__ float g_q[NN * 64];      // pre-scaled by 0.125
__device__ float g_k[NN * 64];
__device__ float g_v[NN * 64];
__device__ float g_x2[NN * 64];

// ---------------- f32x2 helpers ----------------
__device__ __forceinline__ unsigned long long splat2(float x) {
    unsigned long long r;
    asm("mov.b64 %0, {%1, %1};" : "=l"(r) : "f"(x));
    return r;
}
__device__ __forceinline__ unsigned long long fma2(unsigned long long a,
                                                   unsigned long long b,
                                                   unsigned long long c) {
    unsigned long long d;
    asm("fma.rn.f32x2 %0, %1, %2, %3;" : "=l"(d) : "l"(a), "l"(b), "l"(c));
    return d;
}

// ---------------- bucket CSR build (single edge pass, 2 edges/thread) ------------
__global__ void k_fill(const int* __restrict__ ei, int e) {
    int id = (blockIdx.x * blockDim.x + threadIdx.x) * 2;
    if (id + 1 < e) {
        int2 s2 = *(const int2*)(ei + id);
        int2 d2 = *(const int2*)(ei + e + id);
        int r0 = atomicAdd(&g_cur[d2.x], 1);
        if (r0 < CAP) g_srcl[d2.x * CAP + r0] = s2.x;
        int r1 = atomicAdd(&g_cur[d2.y], 1);
        if (r1 < CAP) g_srcl[d2.y * CAP + r1] = s2.y;
    } else if (id < e) {
        int s = ei[id];
        int d = ei[e + id];
        int r = atomicAdd(&g_cur[d], 1);
        if (r < CAP) g_srcl[d * CAP + r] = s;
    }
}

// ---------------- GCN gather: warp per dst, two 16-lane halves (R6) --------------
__global__ __launch_bounds__(256) void k_gcn_gather(const float* __restrict__ xw,
                                                    const float* __restrict__ bias,
                                                    float* __restrict__ out, int n) {
    int w = (blockIdx.x * blockDim.x + threadIdx.x) >> 5;
    if (w >= n) return;
    int lane = threadIdx.x & 31;
    int half = lane >> 4;
    int hl = lane & 15;
    int cnt = g_cur[w];
    if (cnt > CAP) cnt = CAP;
    const int* sl = g_srcl + w * CAP;
    float4 acc = make_float4(0.f, 0.f, 0.f, 0.f);
    int j = half;
    for (; j + 6 < cnt; j += 8) {
        int s0 = sl[j], s1 = sl[j + 2], s2 = sl[j + 4], s3 = sl[j + 6];
        float4 a0 = *(const float4*)(xw + s0 * 64 + hl * 4);
        float4 a1 = *(const float4*)(xw + s1 * 64 + hl * 4);
        float4 a2 = *(const float4*)(xw + s2 * 64 + hl * 4);
        float4 a3 = *(const float4*)(xw + s3 * 64 + hl * 4);
        acc.x += (a0.x + a1.x) + (a2.x + a3.x);
        acc.y += (a0.y + a1.y) + (a2.y + a3.y);
        acc.z += (a0.z + a1.z) + (a2.z + a3.z);
        acc.w += (a0.w + a1.w) + (a2.w + a3.w);
    }
    for (; j < cnt; j += 2) {
        int s = sl[j];
        float4 a = *(const float4*)(xw + s * 64 + hl * 4);
        acc.x += a.x; acc.y += a.y; acc.z += a.z; acc.w += a.w;
    }
    acc.x += __shfl_xor_sync(0xffffffffu, acc.x, 16);
    acc.y += __shfl_xor_sync(0xffffffffu, acc.y, 16);
    acc.z += __shfl_xor_sync(0xffffffffu, acc.z, 16);
    acc.w += __shfl_xor_sync(0xffffffffu, acc.w, 16);
    if (half == 0) {
        float dd = g_dinv[w];
        float4 sv = *(const float4*)(xw + w * 64 + hl * 4);
        float4 b = *(const float4*)(bias + hl * 4);
        float4 o = make_float4((acc.x + sv.x) * dd + b.x, (acc.y + sv.y) * dd + b.y,
                               (acc.z + sv.z) * dd + b.z, (acc.w + sv.w) * dd + b.w);
        *(float4*)(out + w * 64 + hl * 4) = o;
    }
}

// ---------------- fused attention: warp per dst, per-half masks in loops (R6) ----
__global__ __launch_bounds__(256) void k_attn(int n) {
    int w = (blockIdx.x * blockDim.x + threadIdx.x) >> 5;
    if (w >= n) return;
    int lane = threadIdx.x & 31;
    int half = lane >> 4;
    int hl = lane & 15;
    unsigned hmask = half ? 0xffff0000u : 0x0000ffffu;
    int cnt = g_cur[w];
    if (cnt > CAP) cnt = CAP;
    const int* sl = g_srcl + w * CAP;
    float4 q4 = *(const float4*)(g_q + w * 64 + hl * 4);
    float z = 0.f;
    float4 acc = make_float4(0.f, 0.f, 0.f, 0.f);
    int j = half;
    for (; j + 6 < cnt; j += 8) {
        int s0 = sl[j], s1 = sl[j + 2], s2 = sl[j + 4], s3 = sl[j + 6];
        float4 k0 = *(const float4*)(g_k + s0 * 64 + hl * 4);
        float4 k1 = *(const float4*)(g_k + s1 * 64 + hl * 4);
        float4 k2 = *(const float4*)(g_k + s2 * 64 + hl * 4);
        float4 k3 = *(const float4*)(g_k + s3 * 64 + hl * 4);
        float4 v0 = *(const float4*)(g_v + s0 * 64 + hl * 4);
        float4 v1 = *(const float4*)(g_v + s1 * 64 + hl * 4);
        float4 v2 = *(const float4*)(g_v + s2 * 64 + hl * 4);
        float4 v3 = *(const float4*)(g_v + s3 * 64 + hl * 4);
        float p0 = q4.x * k0.x + q4.y * k0.y + q4.z * k0.z + q4.w * k0.w;
        float p1 = q4.x * k1.x + q4.y * k1.y + q4.z * k1.z + q4.w * k1.w;
        float p2 = q4.x * k2.x + q4.y * k2.y + q4.z * k2.z + q4.w * k2.w;
        float p3 = q4.x * k3.x + q4.y * k3.y + q4.z * k3.z + q4.w * k3.w;
#pragma unroll
        for (int o = 8; o > 0; o >>= 1) {
            p0 += __shfl_xor_sync(hmask, p0, o);
            p1 += __shfl_xor_sync(hmask, p1, o);
            p2 += __shfl_xor_sync(hmask, p2, o);
            p3 += __shfl_xor_sync(hmask, p3, o);
        }
        float e0 = __expf(p0), e1 = __expf(p1);
        float e2 = __expf(p2), e3 = __expf(p3);
        z += (e0 + e1) + (e2 + e3);
        acc.x += (v0.x * e0 + v1.x * e1) + (v2.x * e2 + v3.x * e3);
        acc.y += (v0.y * e0 + v1.y * e1) + (v2.y * e2 + v3.y * e3);
        acc.z += (v0.z * e0 + v1.z * e1) + (v2.z * e2 + v3.z * e3);
        acc.w += (v0.w * e0 + v1.w * e1) + (v2.w * e2 + v3.w * e3);
    }
    for (; j < cnt; j += 2) {
        int s = sl[j];
        float4 kv = *(const float4*)(g_k + s * 64 + hl * 4);
        float4 vv = *(const float4*)(g_v + s * 64 + hl * 4);
        float p = q4.x * kv.x + q4.y * kv.y + q4.z * kv.z + q4.w * kv.w;
#pragma unroll
        for (int o = 8; o > 0; o >>= 1) p += __shfl_xor_sync(hmask, p, o);
        float ev = __expf(p);
        z += ev;
        acc.x += vv.x * ev; acc.y += vv.y * ev; acc.z += vv.z * ev; acc.w += vv.w * ev;
    }
    z += __shfl_xor_sync(0xffffffffu, z, 16);
    acc.x += __shfl_xor_sync(0xffffffffu, acc.x, 16);
    acc.y += __shfl_xor_sync(0xffffffffu, acc.y, 16);
    acc.z += __shfl_xor_sync(0xffffffffu, acc.z, 16);
    acc.w += __shfl_xor_sync(0xffffffffu, acc.w, 16);
    if (half == 0) {
        float4 o = *(float4*)(g_x2 + w * 64 + hl * 4);
        if (z > 0.f) {
            float inv = 1.f / z;
            o.x += acc.x * inv; o.y += acc.y * inv;
            o.z += acc.z * inv; o.w += acc.w * inv;
        }
        *(float4*)(g_x2 + w * 64 + hl * 4) = o;
    }
}

// ---- f32x2 GEMM (R6 core). DINV=true: compute sc=rsqrt(g_cur[row]+1), store to
// g_dinv, and prescale (GCN1; removes the k_dinv kernel). DINV=false: read rscale.
template <bool DINV>
__global__ __launch_bounds__(256) void k_gemm2(const float* __restrict__ A,
                                               const float* __restrict__ W,
                                               const float* __restrict__ rscale,
                                               float* __restrict__ C, int n) {
    __shared__ float Ast[64][128];
    __shared__ float Wsm[64][64];
    int tid = threadIdx.x;
    int base = blockIdx.x * 128;
    {
        int wr = tid >> 2, wc = (tid & 3) * 16;
#pragma unroll
        for (int j = 0; j < 4; j++)
            *(float4*)&Wsm[wr][wc + j * 4] = *(const float4*)(W + wr * 64 + wc + j * 4);
    }
    {
        int lr = tid >> 1;
        int lc = (tid & 1) * 32;
        int grow = base + lr;
#pragma unroll
        for (int j = 0; j < 8; j++) {
            float4 a = make_float4(0.f, 0.f, 0.f, 0.f);
            if (grow < n) a = *(const float4*)(A + grow * 64 + lc + j * 4);
            Ast[lc + j * 4 + 0][lr] = a.x;
            Ast[lc + j * 4 + 1][lr] = a.y;
            Ast[lc + j * 4 + 2][lr] = a.z;
            Ast[lc + j * 4 + 3][lr] = a.w;
        }
    }
    __syncthreads();
    int tx = tid & 15, ty = tid >> 4;
    unsigned long long acc[4][4];
#pragma unroll
    for (int i = 0; i < 4; i++)
#pragma unroll
        for (int j = 0; j < 4; j++) acc[i][j] = 0ull;
#pragma unroll 8
    for (int k = 0; k < 64; k++) {
        ulonglong2 ap0 = *(const ulonglong2*)&Ast[k][ty * 8];
        ulonglong2 ap1 = *(const ulonglong2*)&Ast[k][ty * 8 + 4];
        float4 w4 = *(const float4*)&Wsm[k][tx * 4];
        unsigned long long ws0 = splat2(w4.x), ws1 = splat2(w4.y);
        unsigned long long ws2 = splat2(w4.z), ws3 = splat2(w4.w);
        acc[0][0] = fma2(ap0.x, ws0, acc[0][0]);
        acc[0][1] = fma2(ap0.x, ws1, acc[0][1]);
        acc[0][2] = fma2(ap0.x, ws2, acc[0][2]);
        acc[0][3] = fma2(ap0.x, ws3, acc[0][3]);
        acc[1][0] = fma2(ap0.y, ws0, acc[1][0]);
        acc[1][1] = fma2(ap0.y, ws1, acc[1][1]);
        acc[1][2] = fma2(ap0.y, ws2, acc[1][2]);
        acc[1][3] = fma2(ap0.y, ws3, acc[1][3]);
        acc[2][0] = fma2(ap1.x, ws0, acc[2][0]);
        acc[2][1] = fma2(ap1.x, ws1, acc[2][1]);
        acc[2][2] = fma2(ap1.x, ws2, acc[2][2]);
        acc[2][3] = fma2(ap1.x, ws3, acc[2][3]);
        acc[3][0] = fma2(ap1.y, ws0, acc[3][0]);
        acc[3][1] = fma2(ap1.y, ws1, acc[3][1]);
        acc[3][2] = fma2(ap1.y, ws2, acc[3][2]);
        acc[3][3] = fma2(ap1.y, ws3, acc[3][3]);
    }
#pragma unroll
    for (int rp = 0; rp < 4; rp++) {
        float2 c0 = *(float2*)&acc[rp][0];
        float2 c1 = *(float2*)&acc[rp][1];
        float2 c2 = *(float2*)&acc[rp][2];
        float2 c3 = *(float2*)&acc[rp][3];
        int r0 = base + ty * 8 + rp * 2;
        if (r0 < n) {
            float sc;
            if (DINV) {
                sc = rsqrtf((float)(g_cur[r0] + 1));
                if (tx == 0) g_dinv[r0] = sc;
            } else {
                sc = rscale[r0];
            }
            float4 o = make_float4(c0.x * sc, c1.x * sc, c2.x * sc, c3.x * sc);
            *(float4*)(C + r0 * 64 + tx * 4) = o;
        }
        if (r0 + 1 < n) {
            float sc;
            if (DINV) {
                sc = rsqrtf((float)(g_cur[r0 + 1] + 1));
                if (tx == 0) g_dinv[r0 + 1] = sc;
            } else {
                sc = rscale[r0 + 1];
            }
            float4 o = make_float4(c0.y * sc, c1.y * sc, c2.y * sc, c3.y * sc);
            *(float4*)(C + (r0 + 1) * 64 + tx * 4) = o;
        }
    }
}

// ---------------- QKVS GEMM (R6 serial version, proven) ----------------
__global__ __launch_bounds__(256) void k_gemm_qkvs2(const float* __restrict__ A,
        const float* __restrict__ Wq, const float* __restrict__ bq,
        const float* __restrict__ Wk, const float* __restrict__ bk,
        const float* __restrict__ Wv, const float* __restrict__ bv,
        const float* __restrict__ Ws, const float* __restrict__ bs,
        float* __restrict__ Oq, float* __restrict__ Ok,
        float* __restrict__ Ov, float* __restrict__ Os, int n) {
    __shared__ float Ast[64][128];
    __shared__ float Wsm[64][64];
    int tid = threadIdx.x;
    int base = blockIdx.x * 128;
    {
        int lr = tid >> 1;
        int lc = (tid & 1) * 32;
        int grow = base + lr;
#pragma unroll
        for (int j = 0; j < 8; j++) {
            float4 a = make_float4(0.f, 0.f, 0.f, 0.f);
            if (grow < n) a = *(const float4*)(A + grow * 64 + lc + j * 4);
            Ast[lc + j * 4 + 0][lr] = fmaxf(a.x, 0.f);
            Ast[lc + j * 4 + 1][lr] = fmaxf(a.y, 0.f);
            Ast[lc + j * 4 + 2][lr] = fmaxf(a.z, 0.f);
            Ast[lc + j * 4 + 3][lr] = fmaxf(a.w, 0.f);
        }
    }
    int tx = tid & 15, ty = tid >> 4;
    const float* WL[4] = {Wq, Wk, Wv, Ws};
    const float* BL[4] = {bq, bk, bv, bs};
    float*       OL[4] = {Oq, Ok, Ov, Os};
#pragma unroll
    for (int ws = 0; ws < 4; ws++) {
        __syncthreads();
        {
            int wr = tid >> 2, wc = (tid & 3) * 16;
#pragma unroll
            for (int j = 0; j < 4; j++)
                *(float4*)&Wsm[wr][wc + j * 4] =
                    *(const float4*)(WL[ws] + wr * 64 + wc + j * 4);
        }
        __syncthreads();
        unsigned long long acc[4][4];
#pragma unroll
        for (int i = 0; i < 4; i++)
#pragma unroll
            for (int j = 0; j < 4; j++) acc[i][j] = 0ull;
#pragma unroll 8
        for (int k = 0; k < 64; k++) {
            ulonglong2 ap0 = *(const ulonglong2*)&Ast[k][ty * 8];
            ulonglong2 ap1 = *(const ulonglong2*)&Ast[k][ty * 8 + 4];
            float4 w4 = *(const float4*)&Wsm[k][tx * 4];
            unsigned long long s0 = splat2(w4.x), s1 = splat2(w4.y);
            unsigned long long s2 = splat2(w4.z), s3 = splat2(w4.w);
            acc[0][0] = fma2(ap0.x, s0, acc[0][0]);
            acc[0][1] = fma2(ap0.x, s1, acc[0][1]);
            acc[0][2] = fma2(ap0.x, s2, acc[0][2]);
            acc[0][3] = fma2(ap0.x, s3, acc[0][3]);
            acc[1][0] = fma2(ap0.y, s0, acc[1][0]);
            acc[1][1] = fma2(ap0.y, s1, acc[1][1]);
            acc[1][2] = fma2(ap0.y, s2, acc[1][2]);
            acc[1][3] = fma2(ap0.y, s3, acc[1][3]);
            acc[2][0] = fma2(ap1.x, s0, acc[2][0]);
            acc[2][1] = fma2(ap1.x, s1, acc[2][1]);
            acc[2][2] = fma2(ap1.x, s2, acc[2][2]);
            acc[2][3] = fma2(ap1.x, s3, acc[2][3]);
            acc[3][0] = fma2(ap1.y, s0, acc[3][0]);
            acc[3][1] = fma2(ap1.y, s1, acc[3][1]);
            acc[3][2] = fma2(ap1.y, s2, acc[3][2]);
            acc[3][3] = fma2(ap1.y, s3, acc[3][3]);
        }
        float osc = (ws == 0) ? 0.125f : 1.0f;
        float4 b4 = *(const float4*)(BL[ws] + tx * 4);
        float* Co = OL[ws];
#pragma unroll
        for (int rp = 0; rp < 4; rp++) {
            float2 c0 = *(float2*)&acc[rp][0];
            float2 c1 = *(float2*)&acc[rp][1];
            float2 c2 = *(float2*)&acc[rp][2];
            float2 c3 = *(float2*)&acc[rp][3];
            int r0 = base + ty * 8 + rp * 2;
            if (r0 < n) {
                float4 o = make_float4((c0.x + b4.x) * osc, (c1.x + b4.y) * osc,
                                       (c2.x + b4.z) * osc, (c3.x + b4.w) * osc);
                *(float4*)(Co + r0 * 64 + tx * 4) = o;
            }
            if (r0 + 1 < n) {
                float4 o = make_float4((c0.y + b4.x) * osc, (c1.y + b4.y) * osc,
                                       (c2.y + b4.z) * osc, (c3.y + b4.w) * osc);
                *(float4*)(Co + (r0 + 1) * 64 + tx * 4) = o;
            }
        }
    }
}

// ---------------- launch ----------------
extern "C" void kernel_launch(void* const* d_in, const int* in_sizes, int n_in,
                              void* d_out, int out_size) {
    const float* x  = (const float*)d_in[0];
    const int*   ei = (const int*)d_in[1];
    const float* W1 = (const float*)d_in[2];
    const float* b1 = (const float*)d_in[3];
    const float* Wq = (const float*)d_in[4];
    const float* bq = (const float*)d_in[5];
    const float* Wk = (const float*)d_in[6];
    const float* bk = (const float*)d_in[7];
    const float* Wv = (const float*)d_in[8];
    const float* bv = (const float*)d_in[9];
    const float* Ws = (const float*)d_in[10];
    const float* bs = (const float*)d_in[11];
    const float* W2 = (const float*)d_in[12];
    const float* b2 = (const float*)d_in[13];
    float* out = (float*)d_out;

    int n = in_sizes[0] / 64;
    int e = in_sizes[1] / 2;

    float *p_xw, *p_x1, *p_q, *p_k, *p_v, *p_x2, *p_dinv;
    int* p_cur;
    cudaGetSymbolAddress((void**)&p_xw,  g_xw);
    cudaGetSymbolAddress((void**)&p_x1,  g_x1);
    cudaGetSymbolAddress((void**)&p_q,   g_q);
    cudaGetSymbolAddress((void**)&p_k,   g_k);
    cudaGetSymbolAddress((void**)&p_v,   g_v);
    cudaGetSymbolAddress((void**)&p_x2,  g_x2);
    cudaGetSymbolAddress((void**)&p_dinv, g_dinv);
    cudaGetSymbolAddress((void**)&p_cur, g_cur);

    int ebk2 = (e / 2 + TPB) / TPB;
    int gb  = (n + 127) / 128;
    int wb  = (n + 7) / 8;

    // CSR build: memset cursors + single vectorized fill pass (dinv folded into GEMM1)
    cudaMemsetAsync(p_cur, 0, n * sizeof(int));
    k_fill<<<ebk2, TPB>>>(ei, e);

    // GCN1: xw = (x@W1) * rsqrt(deg+1); GEMM also writes g_dinv
    k_gemm2<true><<<gb, 256>>>(x, W1, nullptr, p_xw, n);
    k_gcn_gather<<<wb, 256>>>(p_xw, b1, p_x1, n);

    // TransformerConv (relu fused into A-load; q pre-scaled by 0.125)
    k_gemm_qkvs2<<<gb, 256>>>(p_x1, Wq, bq, Wk, bk, Wv, bv, Ws, bs,
                              p_q, p_k, p_v, p_x2, n);
    k_attn<<<wb, 256>>>(n);

    // GCN2 (reads g_dinv written by GEMM1)
    k_gemm2<false><<<gb, 256>>>(p_x2, W2, p_dinv, p_xw, n);
    k_gcn_gather<<<wb, 256>>>(p_xw, b2, out, n);
}